// round 8
// baseline (speedup 1.0000x reference)
#include <cuda_runtime.h>
#include <cuda_fp16.h>
#include <cstdint>

#define T_TOK 8192
#define D_DIM 1024
#define E_EXP 8
#define I_DIM 3072
#define TRX   16384
#define BM 128
#define BK 32
#define STAGES 3
#define MAXT 144
#define GRID_TILES 136   // max sum ceil(count_e/128)

// ------------------- device scratch (static: no allocation) -------------------
__device__ int    g_topk_idx[TRX];
__device__ float  g_topk_w[TRX];
__device__ int    g_counts[E_EXP];
__device__ int    g_cursor[E_EXP];
__device__ float  g_probs_sum[E_EXP];
__device__ float  g_z2_sum;
__device__ int    g_perm_src[TRX];
__device__ int    g_dest[TRX];
__device__ int    g_tile_e[MAXT];
__device__ int    g_tile_row[MAXT];
__device__ int    g_tile_nrows[MAXT];
__device__ int    g_ntiles;
__device__ __half g_gated[(size_t)TRX * I_DIM];
__device__ float  g_outsorted[(size_t)TRX * D_DIM];
__device__ __half g_w1h[(size_t)E_EXP * D_DIM * I_DIM];
__device__ __half g_w2h[(size_t)E_EXP * D_DIM * I_DIM];
__device__ __half g_w3h[(size_t)E_EXP * I_DIM * D_DIM];
__device__ __half g_xh[(size_t)T_TOK * D_DIM];

__device__ __forceinline__ uint32_t smem_u32(const void* p) {
  return (uint32_t)__cvta_generic_to_shared(p);
}
#define CP_ASYNC16(dst_u32, src_ptr) \
  asm volatile("cp.async.cg.shared.global [%0], [%1], 16;\n" :: "r"(dst_u32), "l"(src_ptr))
#define CP_COMMIT() asm volatile("cp.async.commit_group;\n" ::)
#define CP_WAIT(N)  asm volatile("cp.async.wait_group %0;\n" :: "n"(N))

__device__ __forceinline__ void mma16816(float* c, const uint32_t* a, const uint32_t* b) {
  asm volatile(
    "mma.sync.aligned.m16n8k16.row.col.f32.f16.f16.f32 "
    "{%0,%1,%2,%3}, {%4,%5,%6,%7}, {%8,%9}, {%0,%1,%2,%3};\n"
    : "+f"(c[0]), "+f"(c[1]), "+f"(c[2]), "+f"(c[3])
    : "r"(a[0]), "r"(a[1]), "r"(a[2]), "r"(a[3]), "r"(b[0]), "r"(b[1]));
}
#define LDSM_X4(a, addr) \
  asm volatile("ldmatrix.sync.aligned.m8n8.x4.shared.b16 {%0,%1,%2,%3}, [%4];" \
    : "=r"((a)[0]), "=r"((a)[1]), "=r"((a)[2]), "=r"((a)[3]) : "r"(addr))
#define LDSM_X2T(b, addr) \
  asm volatile("ldmatrix.sync.aligned.m8n8.x2.trans.shared.b16 {%0,%1}, [%2];" \
    : "=r"((b)[0]), "=r"((b)[1]) : "r"(addr))

// ------------------------------- conversion (merged) -------------------------------
#define WN (E_EXP * D_DIM * I_DIM)
#define XN (T_TOK * D_DIM)
#define WBLK (WN / 2048)
#define XBLK (XN / 2048)
#define CVT_BLOCKS (3 * WBLK + XBLK)

__global__ void cvt_all_kernel(const float* __restrict__ w1, const float* __restrict__ w2,
                               const float* __restrict__ w3, const float* __restrict__ x) {
  int b = blockIdx.x;
  const float* src;
  __half* dst;
  if (b < WBLK)            { src = w1; dst = g_w1h; }
  else if (b < 2 * WBLK)   { src = w2; dst = g_w2h; b -= WBLK; }
  else if (b < 3 * WBLK)   { src = w3; dst = g_w3h; b -= 2 * WBLK; }
  else                     { src = x;  dst = g_xh;  b -= 3 * WBLK; }
  size_t i = ((size_t)b * 256 + threadIdx.x) * 8;
  float4 a = *(const float4*)(src + i);
  float4 c = *(const float4*)(src + i + 4);
  __align__(16) __half2 h[4];
  h[0] = __floats2half2_rn(a.x, a.y);
  h[1] = __floats2half2_rn(a.z, a.w);
  h[2] = __floats2half2_rn(c.x, c.y);
  h[3] = __floats2half2_rn(c.z, c.w);
  *(uint4*)(dst + i) = *(uint4*)h;
}

// ------------------------------- small kernels --------------------------------
__global__ void zero_kernel() {
  int t = threadIdx.x;
  if (t < E_EXP) { g_counts[t] = 0; g_cursor[t] = 0; g_probs_sum[t] = 0.f; }
  if (t == 0) { g_z2_sum = 0.f; g_ntiles = 0; }
}

__global__ void router_kernel(const float* __restrict__ x, const float* __restrict__ rw) {
  int warp = threadIdx.x >> 5;
  int lane = threadIdx.x & 31;
  int token = blockIdx.x * 8 + warp;
  const float* xr = x + (size_t)token * D_DIM;
  float acc[E_EXP];
#pragma unroll
  for (int e = 0; e < E_EXP; e++) acc[e] = 0.f;
  for (int i = lane; i < D_DIM; i += 32) {
    float xv = xr[i];
    const float4* w4 = reinterpret_cast<const float4*>(rw + (size_t)i * E_EXP);
    float4 wa = w4[0], wb = w4[1];
    acc[0] += xv * wa.x; acc[1] += xv * wa.y; acc[2] += xv * wa.z; acc[3] += xv * wa.w;
    acc[4] += xv * wb.x; acc[5] += xv * wb.y; acc[6] += xv * wb.z; acc[7] += xv * wb.w;
  }
#pragma unroll
  for (int e = 0; e < E_EXP; e++) {
#pragma unroll
    for (int o = 16; o > 0; o >>= 1) acc[e] += __shfl_xor_sync(0xffffffffu, acc[e], o);
  }
  if (lane == 0) {
    float m = acc[0];
#pragma unroll
    for (int e = 1; e < E_EXP; e++) m = fmaxf(m, acc[e]);
    float p[E_EXP]; float se = 0.f;
#pragma unroll
    for (int e = 0; e < E_EXP; e++) { p[e] = expf(acc[e] - m); se += p[e]; }
    float inv = 1.f / se;
#pragma unroll
    for (int e = 0; e < E_EXP; e++) p[e] *= inv;
    float z = m + logf(se);
    atomicAdd(&g_z2_sum, z * z);
#pragma unroll
    for (int e = 0; e < E_EXP; e++) atomicAdd(&g_probs_sum[e], p[e]);
    int i0 = 0;
#pragma unroll
    for (int e = 1; e < E_EXP; e++) if (acc[e] > acc[i0]) i0 = e;
    int i1 = (i0 == 0) ? 1 : 0;
#pragma unroll
    for (int e = 0; e < E_EXP; e++) if (e != i0 && acc[e] > acc[i1]) i1 = e;
    float s = p[i0] + p[i1];
    g_topk_idx[token * 2 + 0] = i0;
    g_topk_idx[token * 2 + 1] = i1;
    g_topk_w[token * 2 + 0] = p[i0] / s;
    g_topk_w[token * 2 + 1] = p[i1] / s;
    atomicAdd(&g_counts[i0], 1);
    atomicAdd(&g_counts[i1], 1);
  }
}

__global__ void scan_kernel() {
  if (threadIdx.x == 0) {
    int off = 0, nt = 0;
    for (int e = 0; e < E_EXP; e++) {
      g_cursor[e] = off;
      int c = g_counts[e];
      for (int r = 0; r < c; r += BM) {
        g_tile_e[nt] = e;
        g_tile_row[nt] = off + r;
        g_tile_nrows[nt] = (c - r < BM) ? (c - r) : BM;
        nt++;
      }
      off += c;
    }
    g_ntiles = nt;
  }
}

__global__ void scatter_kernel() {
  int i = blockIdx.x * 256 + threadIdx.x;
  if (i < TRX) {
    int e = g_topk_idx[i];
    int pos = atomicAdd(&g_cursor[e], 1);
    g_perm_src[pos] = i >> 1;
    g_dest[i] = pos;
  }
}

// ------------------- smem layout -------------------
#define A_ST 10240
#define B1_ST 4608
#define G1_A  1024
#define G1_B1 (G1_A + STAGES * A_ST)
#define G1_B2 (G1_B1 + STAGES * B1_ST)
#define G1_SMEM (G1_B2 + STAGES * B1_ST)  // 59392
#define B2_ST 8704
#define G2_A 0
#define G2_B (STAGES * A_ST)
#define G2_SMEM (G2_B + STAGES * B2_ST)   // 56832

// ------------------- GEMM1: gated = silu(Xg*W1) * (Xg*W2) -------------------
// BM=128, BN=64, 256 threads, 2 CTAs/SM, 3-stage, 1 barrier/iter.
// Inner loop: all LDSMs issued, then all MMAs (latency hiding by issue train).
__global__ __launch_bounds__(256, 2)
void gemm1_kernel() {
  int tile = blockIdx.y;
  if (tile >= g_ntiles) return;
  extern __shared__ char sm[];
  const int tid = threadIdx.x;
  const int e = g_tile_e[tile];
  const int row0 = g_tile_row[tile];
  const int nrows = g_tile_nrows[tile];
  const int n0 = blockIdx.x * 64;
  const __half* __restrict__ W1 = g_w1h + (size_t)e * D_DIM * I_DIM;
  const __half* __restrict__ W2 = g_w2h + (size_t)e * D_DIM * I_DIM;

  int* rowtok = (int*)sm;
  if (tid < BM) {
    int r = row0 + tid;
    rowtok[tid] = g_perm_src[r < TRX ? r : TRX - 1];
  }
  __syncthreads();

  const int ar0 = tid >> 2,           ac0 = (tid & 3) << 3;
  const int ar1 = (tid + 256) >> 2,   ac1 = ((tid + 256) & 3) << 3;
  const __half* a0p = g_xh + (size_t)rowtok[ar0] * D_DIM + ac0;
  const __half* a1p = g_xh + (size_t)rowtok[ar1] * D_DIM + ac1;
  const uint32_t a0d = smem_u32(sm + G1_A) + (ar0 * 40 + ac0) * 2;
  const uint32_t a1d = smem_u32(sm + G1_A) + (ar1 * 40 + ac1) * 2;
  const int br = tid >> 3, bc = (tid & 7) << 3;
  const __half* b1p = W1 + (size_t)br * I_DIM + n0 + bc;
  const __half* b2p = W2 + (size_t)br * I_DIM + n0 + bc;
  const uint32_t b1d = smem_u32(sm + G1_B1) + (br * 72 + bc) * 2;
  const uint32_t b2d = smem_u32(sm + G1_B2) + (br * 72 + bc) * 2;

  float c1[2][4][4], c2[2][4][4];
#pragma unroll
  for (int i = 0; i < 2; i++)
#pragma unroll
    for (int j = 0; j < 4; j++)
#pragma unroll
      for (int q = 0; q < 4; q++) { c1[i][j][q] = 0.f; c2[i][j][q] = 0.f; }

  const int lane = tid & 31;
  const int wid = tid >> 5;
  const int wm = wid >> 1;
  const int wn = wid & 1;

  const int NK = D_DIM / BK;  // 32
#pragma unroll
  for (int s = 0; s < STAGES - 1; s++) {
    int k0 = s * BK;
    CP_ASYNC16(a0d + s * A_ST, a0p + k0);
    CP_ASYNC16(a1d + s * A_ST, a1p + k0);
    CP_ASYNC16(b1d + s * B1_ST, b1p + (size_t)k0 * I_DIM);
    CP_ASYNC16(b2d + s * B1_ST, b2p + (size_t)k0 * I_DIM);
    CP_COMMIT();
  }

#pragma unroll 1
  for (int it = 0; it < NK; it++) {
    const int buf = it % STAGES;
    CP_WAIT(STAGES - 2);
    __syncthreads();
    {
      int pf = it + STAGES - 1;
      if (pf < NK) {
        int sb = pf % STAGES;
        int k0 = pf * BK;
        CP_ASYNC16(a0d + sb * A_ST, a0p + k0);
        CP_ASYNC16(a1d + sb * A_ST, a1p + k0);
        CP_ASYNC16(b1d + sb * B1_ST, b1p + (size_t)k0 * I_DIM);
        CP_ASYNC16(b2d + sb * B1_ST, b2p + (size_t)k0 * I_DIM);
      }
      CP_COMMIT();
    }
    const __half* As  = (const __half*)(sm + G1_A  + buf * A_ST);
    const __half* B1s = (const __half*)(sm + G1_B1 + buf * B1_ST);
    const __half* B2s = (const __half*)(sm + G1_B2 + buf * B1_ST);

#pragma unroll
    for (int kk = 0; kk < BK; kk += 16) {
      // ---------- load phase: 2 A.x4 + 8 B.x2 back-to-back ----------
      uint32_t a[2][4], b1[4][2], b2[4][2];
#pragma unroll
      for (int mf = 0; mf < 2; mf++) {
        uint32_t ad = smem_u32(As + (size_t)(wm * 32 + mf * 16 + (lane & 15)) * 40
                               + kk + ((lane >> 4) << 3));
        LDSM_X4(a[mf], ad);
      }
#pragma unroll
      for (int nf = 0; nf < 4; nf++) {
        uint32_t ad1 = smem_u32(B1s + (size_t)(kk + (lane & 15)) * 72 + wn * 32 + nf * 8);
        LDSM_X2T(b1[nf], ad1);
      }
#pragma unroll
      for (int nf = 0; nf < 4; nf++) {
        uint32_t ad2 = smem_u32(B2s + (size_t)(kk + (lane & 15)) * 72 + wn * 32 + nf * 8);
        LDSM_X2T(b2[nf], ad2);
      }
      // ---------- math phase: 16 MMAs ----------
#pragma unroll
      for (int nf = 0; nf < 4; nf++) {
        mma16816(c1[0][nf], a[0], b1[nf]);
        mma16816(c1[1][nf], a[1], b1[nf]);
      }
#pragma unroll
      for (int nf = 0; nf < 4; nf++) {
        mma16816(c2[0][nf], a[0], b2[nf]);
        mma16816(c2[1][nf], a[1], b2[nf]);
      }
    }
  }

  const int grp = lane >> 2;
  const int qp  = (lane & 3) << 1;
#pragma unroll
  for (int mf = 0; mf < 2; mf++) {
#pragma unroll
    for (int nf = 0; nf < 4; nf++) {
#pragma unroll
      for (int h8 = 0; h8 < 2; h8++) {
        int rl = wm * 32 + mf * 16 + grp + h8 * 8;
        if (rl < nrows) {
          float h1a = c1[mf][nf][h8 * 2 + 0];
          float h1b = c1[mf][nf][h8 * 2 + 1];
          float h2a = c2[mf][nf][h8 * 2 + 0];
          float h2b = c2[mf][nf][h8 * 2 + 1];
          float ga = (h1a / (1.f + __expf(-h1a))) * h2a;
          float gb = (h1b / (1.f + __expf(-h1b))) * h2b;
          size_t o = (size_t)(row0 + rl) * I_DIM + (n0 + wn * 32 + nf * 8 + qp);
          *(__half2*)&g_gated[o] = __floats2half2_rn(ga, gb);
        }
      }
    }
  }
}

// ------------------- GEMM2: out_sorted = gated * W3 -------------------
// BM=128, BN=128, 256 threads: warp tile 64x32; load-phase/math-phase inner loop
__global__ __launch_bounds__(256, 2)
void gemm2_kernel() {
  int tile = blockIdx.y;
  if (tile >= g_ntiles) return;
  extern __shared__ char sm[];
  const int tid = threadIdx.x;
  const int e = g_tile_e[tile];
  const int row0 = g_tile_row[tile];
  const int nrows = g_tile_nrows[tile];
  const int n0 = blockIdx.x * 128;
  const __half* __restrict__ W3 = g_w3h + (size_t)e * I_DIM * D_DIM;

  const int ar0 = tid >> 2,         ac0 = (tid & 3) << 3;
  const int ar1 = (tid + 256) >> 2, ac1 = ((tid + 256) & 3) << 3;
  int s0 = row0 + ar0; if (s0 >= TRX) s0 = TRX - 1;
  int s1 = row0 + ar1; if (s1 >= TRX) s1 = TRX - 1;
  const __half* a0p = g_gated + (size_t)s0 * I_DIM + ac0;
  const __half* a1p = g_gated + (size_t)s1 * I_DIM + ac1;
  const uint32_t a0d = smem_u32(sm + G2_A) + (ar0 * 40 + ac0) * 2;
  const uint32_t a1d = smem_u32(sm + G2_A) + (ar1 * 40 + ac1) * 2;
  const int br0 = tid >> 4,         bc0 = (tid & 15) << 3;
  const int br1 = (tid + 256) >> 4, bc1 = ((tid + 256) & 15) << 3;
  const __half* b0p = W3 + (size_t)br0 * D_DIM + n0 + bc0;
  const __half* b1p = W3 + (size_t)br1 * D_DIM + n0 + bc1;
  const uint32_t b0d = smem_u32(sm + G2_B) + (br0 * 136 + bc0) * 2;
  const uint32_t b1d = smem_u32(sm + G2_B) + (br1 * 136 + bc1) * 2;

  float c[4][4][4];
#pragma unroll
  for (int i = 0; i < 4; i++)
#pragma unroll
    for (int j = 0; j < 4; j++)
#pragma unroll
      for (int q = 0; q < 4; q++) c[i][j][q] = 0.f;

  const int lane = tid & 31;
  const int wid = tid >> 5;
  const int wm = wid >> 2;
  const int wn = wid & 3;

  const int NK = I_DIM / BK;  // 96
#pragma unroll
  for (int s = 0; s < STAGES - 1; s++) {
    int k0 = s * BK;
    CP_ASYNC16(a0d + s * A_ST, a0p + k0);
    CP_ASYNC16(a1d + s * A_ST, a1p + k0);
    CP_ASYNC16(b0d + s * B2_ST, b0p + (size_t)k0 * D_DIM);
    CP_ASYNC16(b1d + s * B2_ST, b1p + (size_t)k0 * D_DIM);
    CP_COMMIT();
  }

#pragma unroll 1
  for (int it = 0; it < NK; it++) {
    const int buf = it % STAGES;
    CP_WAIT(STAGES - 2);
    __syncthreads();
    {
      int pf = it + STAGES - 1;
      if (pf < NK) {
        int sb = pf % STAGES;
        int k0 = pf * BK;
        CP_ASYNC16(a0d + sb * A_ST, a0p + k0);
        CP_ASYNC16(a1d + sb * A_ST, a1p + k0);
        CP_ASYNC16(b0d + sb * B2_ST, b0p + (size_t)k0 * D_DIM);
        CP_ASYNC16(b1d + sb * B2_ST, b1p + (size_t)k0 * D_DIM);
      }
      CP_COMMIT();
    }
    const __half* As = (const __half*)(sm + G2_A + buf * A_ST);
    const __half* Bs = (const __half*)(sm + G2_B + buf * B2_ST);

#pragma unroll
    for (int kk = 0; kk < BK; kk += 16) {
      // ---------- load phase: 4 A.x4 + 4 B.x2 ----------
      uint32_t a[4][4], b[4][2];
#pragma unroll
      for (int mf = 0; mf < 4; mf++) {
        uint32_t ad = smem_u32(As + (size_t)(wm * 64 + mf * 16 + (lane & 15)) * 40
                               + kk + ((lane >> 4) << 3));
        LDSM_X4(a[mf], ad);
      }
#pragma unroll
      for (int nf = 0; nf < 4; nf++) {
        uint32_t ad = smem_u32(Bs + (size_t)(kk + (lane & 15)) * 136 + wn * 32 + nf * 8);
        LDSM_X2T(b[nf], ad);
      }
      // ---------- math phase: 16 MMAs ----------
#pragma unroll
      for (int nf = 0; nf < 4; nf++) {
#pragma unroll
        for (int mf = 0; mf < 4; mf++) mma16816(c[mf][nf], a[mf], b[nf]);
      }
    }
  }

  const int grp = lane >> 2;
  const int qp  = (lane & 3) << 1;
#pragma unroll
  for (int mf = 0; mf < 4; mf++) {
#pragma unroll
    for (int nf = 0; nf < 4; nf++) {
#pragma unroll
      for (int h8 = 0; h8 < 2; h8++) {
        int rl = wm * 64 + mf * 16 + grp + h8 * 8;
        if (rl < nrows) {
          size_t o = (size_t)(row0 + rl) * D_DIM + (n0 + wn * 32 + nf * 8 + qp);
          float2 v = make_float2(c[mf][nf][h8 * 2 + 0], c[mf][nf][h8 * 2 + 1]);
          *(float2*)&g_outsorted[o] = v;
        }
      }
    }
  }
}

// ------------------- combine + aux -------------------
__global__ void combine_kernel(float* __restrict__ out) {
  int t = blockIdx.x;
  int p0 = g_dest[t * 2 + 0];
  int p1 = g_dest[t * 2 + 1];
  float w0 = g_topk_w[t * 2 + 0];
  float w1 = g_topk_w[t * 2 + 1];
  const float4* s0 = (const float4*)&g_outsorted[(size_t)p0 * D_DIM];
  const float4* s1 = (const float4*)&g_outsorted[(size_t)p1 * D_DIM];
  float4* o = (float4*)(out + (size_t)t * D_DIM);
  int i = threadIdx.x;
  float4 a = s0[i], b = s1[i];
  float4 r;
  r.x = w0 * a.x + w1 * b.x;
  r.y = w0 * a.y + w1 * b.y;
  r.z = w0 * a.z + w1 * b.z;
  r.w = w0 * a.w + w1 * b.w;
  o[i] = r;
}

__global__ void aux_kernel(float* __restrict__ aux) {
  int t = threadIdx.x;
  if (t < E_EXP) aux[t] = (float)g_counts[t] / (float)TRX;
  if (t == 0) {
    float lbl = 0.f;
    for (int e = 0; e < E_EXP; e++) {
      float f = ((float)g_counts[e] / (float)TRX) * ((float)E_EXP / 2.f);
      float pm = g_probs_sum[e] / (float)T_TOK;
      lbl += f * pm;
    }
    aux[E_EXP]     = 0.01f  * lbl;
    aux[E_EXP + 1] = 0.001f * (g_z2_sum / (float)T_TOK);
  }
}

// ------------------------------- launch -------------------------------
extern "C" void kernel_launch(void* const* d_in, const int* in_sizes, int n_in,
                              void* d_out, int out_size) {
  const float* x  = (const float*)d_in[0];
  const float* rw = (const float*)d_in[1];
  const float* w1 = (const float*)d_in[2];
  const float* w2 = (const float*)d_in[3];
  const float* w3 = (const float*)d_in[4];
  float* out = (float*)d_out;

  cudaFuncSetAttribute(gemm1_kernel, cudaFuncAttributeMaxDynamicSharedMemorySize, G1_SMEM);
  cudaFuncSetAttribute(gemm2_kernel, cudaFuncAttributeMaxDynamicSharedMemorySize, G2_SMEM);

  cvt_all_kernel<<<CVT_BLOCKS, 256>>>(w1, w2, w3, x);
  zero_kernel<<<1, 32>>>();
  router_kernel<<<T_TOK / 8, 256>>>(x, rw);
  scan_kernel<<<1, 1>>>();
  scatter_kernel<<<TRX / 256, 256>>>();
  gemm1_kernel<<<dim3(I_DIM / 64, GRID_TILES), 256, G1_SMEM>>>();
  gemm2_kernel<<<dim3(D_DIM / 128, GRID_TILES), 256, G2_SMEM>>>();
  combine_kernel<<<T_TOK, 256>>>(out);
  aux_kernel<<<1, 32>>>(out + (size_t)T_TOK * D_DIM);
}

// round 9
// speedup vs baseline: 1.5965x; 1.5965x over previous
#include <cuda_runtime.h>
#include <cuda_fp16.h>
#include <cstdint>

#define T_TOK 8192
#define D_DIM 1024
#define E_EXP 8
#define I_DIM 3072
#define TRX   16384
#define BM 128
#define BK 64
#define STAGES 3
#define MAXT 144
#define GRID_TILES 136   // max sum ceil(count_e/128)

// ------------------- device scratch (static: no allocation) -------------------
__device__ int    g_topk_idx[TRX];
__device__ float  g_topk_w[TRX];
__device__ int    g_counts[E_EXP];
__device__ int    g_cursor[E_EXP];
__device__ float  g_probs_sum[E_EXP];
__device__ float  g_z2_sum;
__device__ int    g_perm_src[TRX];
__device__ int    g_dest[TRX];
__device__ int    g_tile_e[MAXT];
__device__ int    g_tile_row[MAXT];
__device__ int    g_tile_nrows[MAXT];
__device__ int    g_ntiles;
__device__ __half g_gated[(size_t)TRX * I_DIM];
__device__ float  g_outsorted[(size_t)TRX * D_DIM];
__device__ __half g_w1h[(size_t)E_EXP * D_DIM * I_DIM];
__device__ __half g_w2h[(size_t)E_EXP * D_DIM * I_DIM];
__device__ __half g_w3h[(size_t)E_EXP * I_DIM * D_DIM];
__device__ __half g_xh[(size_t)T_TOK * D_DIM];

__device__ __forceinline__ uint32_t smem_u32(const void* p) {
  return (uint32_t)__cvta_generic_to_shared(p);
}
#define CP_ASYNC16(dst_u32, src_ptr) \
  asm volatile("cp.async.cg.shared.global [%0], [%1], 16;\n" :: "r"(dst_u32), "l"(src_ptr))
#define CP_COMMIT() asm volatile("cp.async.commit_group;\n" ::)
#define CP_WAIT(N)  asm volatile("cp.async.wait_group %0;\n" :: "n"(N))

__device__ __forceinline__ void mma16816(float* c, const uint32_t* a, const uint32_t* b) {
  asm volatile(
    "mma.sync.aligned.m16n8k16.row.col.f32.f16.f16.f32 "
    "{%0,%1,%2,%3}, {%4,%5,%6,%7}, {%8,%9}, {%0,%1,%2,%3};\n"
    : "+f"(c[0]), "+f"(c[1]), "+f"(c[2]), "+f"(c[3])
    : "r"(a[0]), "r"(a[1]), "r"(a[2]), "r"(a[3]), "r"(b[0]), "r"(b[1]));
}

// ------------------------------- conversion (merged) -------------------------------
#define WN (E_EXP * D_DIM * I_DIM)
#define XN (T_TOK * D_DIM)
#define WBLK (WN / 2048)
#define XBLK (XN / 2048)
#define CVT_BLOCKS (3 * WBLK + XBLK)

__global__ void cvt_all_kernel(const float* __restrict__ w1, const float* __restrict__ w2,
                               const float* __restrict__ w3, const float* __restrict__ x) {
  int b = blockIdx.x;
  const float* src;
  __half* dst;
  if (b < WBLK)            { src = w1; dst = g_w1h; }
  else if (b < 2 * WBLK)   { src = w2; dst = g_w2h; b -= WBLK; }
  else if (b < 3 * WBLK)   { src = w3; dst = g_w3h; b -= 2 * WBLK; }
  else                     { src = x;  dst = g_xh;  b -= 3 * WBLK; }
  size_t i = ((size_t)b * 256 + threadIdx.x) * 8;
  float4 a = *(const float4*)(src + i);
  float4 c = *(const float4*)(src + i + 4);
  __align__(16) __half2 h[4];
  h[0] = __floats2half2_rn(a.x, a.y);
  h[1] = __floats2half2_rn(a.z, a.w);
  h[2] = __floats2half2_rn(c.x, c.y);
  h[3] = __floats2half2_rn(c.z, c.w);
  *(uint4*)(dst + i) = *(uint4*)h;
}

// ------------------------------- small kernels --------------------------------
__global__ void zero_kernel() {
  int t = threadIdx.x;
  if (t < E_EXP) { g_counts[t] = 0; g_cursor[t] = 0; g_probs_sum[t] = 0.f; }
  if (t == 0) { g_z2_sum = 0.f; g_ntiles = 0; }
}

__global__ void router_kernel(const float* __restrict__ x, const float* __restrict__ rw) {
  int warp = threadIdx.x >> 5;
  int lane = threadIdx.x & 31;
  int token = blockIdx.x * 8 + warp;
  const float* xr = x + (size_t)token * D_DIM;
  float acc[E_EXP];
#pragma unroll
  for (int e = 0; e < E_EXP; e++) acc[e] = 0.f;
  for (int i = lane; i < D_DIM; i += 32) {
    float xv = xr[i];
    const float4* w4 = reinterpret_cast<const float4*>(rw + (size_t)i * E_EXP);
    float4 wa = w4[0], wb = w4[1];
    acc[0] += xv * wa.x; acc[1] += xv * wa.y; acc[2] += xv * wa.z; acc[3] += xv * wa.w;
    acc[4] += xv * wb.x; acc[5] += xv * wb.y; acc[6] += xv * wb.z; acc[7] += xv * wb.w;
  }
#pragma unroll
  for (int e = 0; e < E_EXP; e++) {
#pragma unroll
    for (int o = 16; o > 0; o >>= 1) acc[e] += __shfl_xor_sync(0xffffffffu, acc[e], o);
  }
  if (lane == 0) {
    float m = acc[0];
#pragma unroll
    for (int e = 1; e < E_EXP; e++) m = fmaxf(m, acc[e]);
    float p[E_EXP]; float se = 0.f;
#pragma unroll
    for (int e = 0; e < E_EXP; e++) { p[e] = expf(acc[e] - m); se += p[e]; }
    float inv = 1.f / se;
#pragma unroll
    for (int e = 0; e < E_EXP; e++) p[e] *= inv;
    float z = m + logf(se);
    atomicAdd(&g_z2_sum, z * z);
#pragma unroll
    for (int e = 0; e < E_EXP; e++) atomicAdd(&g_probs_sum[e], p[e]);
    int i0 = 0;
#pragma unroll
    for (int e = 1; e < E_EXP; e++) if (acc[e] > acc[i0]) i0 = e;
    int i1 = (i0 == 0) ? 1 : 0;
#pragma unroll
    for (int e = 0; e < E_EXP; e++) if (e != i0 && acc[e] > acc[i1]) i1 = e;
    float s = p[i0] + p[i1];
    g_topk_idx[token * 2 + 0] = i0;
    g_topk_idx[token * 2 + 1] = i1;
    g_topk_w[token * 2 + 0] = p[i0] / s;
    g_topk_w[token * 2 + 1] = p[i1] / s;
    atomicAdd(&g_counts[i0], 1);
    atomicAdd(&g_counts[i1], 1);
  }
}

__global__ void scan_kernel() {
  if (threadIdx.x == 0) {
    int off = 0, nt = 0;
    for (int e = 0; e < E_EXP; e++) {
      g_cursor[e] = off;
      int c = g_counts[e];
      for (int r = 0; r < c; r += BM) {
        g_tile_e[nt] = e;
        g_tile_row[nt] = off + r;
        g_tile_nrows[nt] = (c - r < BM) ? (c - r) : BM;
        nt++;
      }
      off += c;
    }
    g_ntiles = nt;
  }
}

__global__ void scatter_kernel() {
  int i = blockIdx.x * 256 + threadIdx.x;
  if (i < TRX) {
    int e = g_topk_idx[i];
    int pos = atomicAdd(&g_cursor[e], 1);
    g_perm_src[pos] = i >> 1;
    g_dest[i] = pos;
  }
}

// ------------------- smem layout (BK=64) -------------------
// A stage: 128 rows x 72 halves (144B pitch) = 18432 B
#define A_ST 18432
// GEMM1 B stage: 64 rows x 72 halves = 9216 B per matrix
#define B1_ST 9216
#define G1_A  1024
#define G1_B1 (G1_A + STAGES * A_ST)       // 56320
#define G1_B2 (G1_B1 + STAGES * B1_ST)     // 83968
#define G1_SMEM (G1_B2 + STAGES * B1_ST)   // 111616 (109 KB, 2 CTAs = 218 KB)
// GEMM2 B stage: 64 rows x 136 halves = 17408 B
#define B2_ST 17408
#define G2_A 0
#define G2_B (STAGES * A_ST)               // 55296
#define G2_SMEM (G2_B + STAGES * B2_ST)    // 107520 (105 KB)

// ------------------- GEMM1: gated = silu(Xg*W1) * (Xg*W2) -------------------
// BM=128, BN=64, BK=64, 3-stage, 1 barrier/iter, interleaved LDSM->MMA (proven order)
__global__ __launch_bounds__(256, 2)
void gemm1_kernel() {
  int tile = blockIdx.y;
  if (tile >= g_ntiles) return;
  extern __shared__ char sm[];
  const int tid = threadIdx.x;
  const int e = g_tile_e[tile];
  const int row0 = g_tile_row[tile];
  const int nrows = g_tile_nrows[tile];
  const int n0 = blockIdx.x * 64;
  const __half* __restrict__ W1 = g_w1h + (size_t)e * D_DIM * I_DIM;
  const __half* __restrict__ W2 = g_w2h + (size_t)e * D_DIM * I_DIM;

  int* rowtok = (int*)sm;
  if (tid < BM) {
    int r = row0 + tid;
    rowtok[tid] = g_perm_src[r < TRX ? r : TRX - 1];
  }
  __syncthreads();

  // A: 1024 16B-chunks (128 rows x 8), 4 per thread
  const __half* ap[4];
  uint32_t ad[4];
#pragma unroll
  for (int q = 0; q < 4; q++) {
    int id = tid + q * 256;
    int r = id >> 3, cc = (id & 7) << 3;
    ap[q] = g_xh + (size_t)rowtok[r] * D_DIM + cc;
    ad[q] = smem_u32(sm + G1_A) + (r * 72 + cc) * 2;
  }
  // B: 512 chunks per matrix (64 rows x 8), 2 per thread per matrix
  const __half* b1p[2]; const __half* b2p[2];
  uint32_t b1d[2], b2d[2];
#pragma unroll
  for (int q = 0; q < 2; q++) {
    int id = tid + q * 256;
    int r = id >> 3, cc = (id & 7) << 3;
    b1p[q] = W1 + (size_t)r * I_DIM + n0 + cc;
    b2p[q] = W2 + (size_t)r * I_DIM + n0 + cc;
    b1d[q] = smem_u32(sm + G1_B1) + (r * 72 + cc) * 2;
    b2d[q] = smem_u32(sm + G1_B2) + (r * 72 + cc) * 2;
  }

  float c1[2][4][4], c2[2][4][4];
#pragma unroll
  for (int i = 0; i < 2; i++)
#pragma unroll
    for (int j = 0; j < 4; j++)
#pragma unroll
      for (int q = 0; q < 4; q++) { c1[i][j][q] = 0.f; c2[i][j][q] = 0.f; }

  const int lane = tid & 31;
  const int wid = tid >> 5;
  const int wm = wid >> 1;
  const int wn = wid & 1;

  const int NK = D_DIM / BK;  // 16
#pragma unroll
  for (int s = 0; s < STAGES - 1; s++) {
    int k0 = s * BK;
#pragma unroll
    for (int q = 0; q < 4; q++) CP_ASYNC16(ad[q] + s * A_ST, ap[q] + k0);
#pragma unroll
    for (int q = 0; q < 2; q++) {
      CP_ASYNC16(b1d[q] + s * B1_ST, b1p[q] + (size_t)k0 * I_DIM);
      CP_ASYNC16(b2d[q] + s * B1_ST, b2p[q] + (size_t)k0 * I_DIM);
    }
    CP_COMMIT();
  }

#pragma unroll 1
  for (int it = 0; it < NK; it++) {
    const int buf = it % STAGES;
    CP_WAIT(STAGES - 2);
    __syncthreads();
    {
      int pf = it + STAGES - 1;
      if (pf < NK) {
        int sb = pf % STAGES;
        int k0 = pf * BK;
#pragma unroll
        for (int q = 0; q < 4; q++) CP_ASYNC16(ad[q] + sb * A_ST, ap[q] + k0);
#pragma unroll
        for (int q = 0; q < 2; q++) {
          CP_ASYNC16(b1d[q] + sb * B1_ST, b1p[q] + (size_t)k0 * I_DIM);
          CP_ASYNC16(b2d[q] + sb * B1_ST, b2p[q] + (size_t)k0 * I_DIM);
        }
      }
      CP_COMMIT();
    }
    const __half* As  = (const __half*)(sm + G1_A  + buf * A_ST);
    const __half* B1s = (const __half*)(sm + G1_B1 + buf * B1_ST);
    const __half* B2s = (const __half*)(sm + G1_B2 + buf * B1_ST);

#pragma unroll
    for (int kk = 0; kk < BK; kk += 16) {
      uint32_t a[2][4];
#pragma unroll
      for (int mf = 0; mf < 2; mf++) {
        uint32_t aad = smem_u32(As + (size_t)(wm * 32 + mf * 16 + (lane & 15)) * 72
                                + kk + ((lane >> 4) << 3));
        asm volatile("ldmatrix.sync.aligned.m8n8.x4.shared.b16 {%0,%1,%2,%3}, [%4];"
          : "=r"(a[mf][0]), "=r"(a[mf][1]), "=r"(a[mf][2]), "=r"(a[mf][3]) : "r"(aad));
      }
#pragma unroll
      for (int nf = 0; nf < 4; nf++) {
        uint32_t b[2];
        uint32_t ad1 = smem_u32(B1s + (size_t)(kk + (lane & 15)) * 72 + wn * 32 + nf * 8);
        asm volatile("ldmatrix.sync.aligned.m8n8.x2.trans.shared.b16 {%0,%1}, [%2];"
          : "=r"(b[0]), "=r"(b[1]) : "r"(ad1));
        mma16816(c1[0][nf], a[0], b);
        mma16816(c1[1][nf], a[1], b);
        uint32_t ad2 = smem_u32(B2s + (size_t)(kk + (lane & 15)) * 72 + wn * 32 + nf * 8);
        asm volatile("ldmatrix.sync.aligned.m8n8.x2.trans.shared.b16 {%0,%1}, [%2];"
          : "=r"(b[0]), "=r"(b[1]) : "r"(ad2));
        mma16816(c2[0][nf], a[0], b);
        mma16816(c2[1][nf], a[1], b);
      }
    }
  }

  const int grp = lane >> 2;
  const int qp  = (lane & 3) << 1;
#pragma unroll
  for (int mf = 0; mf < 2; mf++) {
#pragma unroll
    for (int nf = 0; nf < 4; nf++) {
#pragma unroll
      for (int h8 = 0; h8 < 2; h8++) {
        int rl = wm * 32 + mf * 16 + grp + h8 * 8;
        if (rl < nrows) {
          float h1a = c1[mf][nf][h8 * 2 + 0];
          float h1b = c1[mf][nf][h8 * 2 + 1];
          float h2a = c2[mf][nf][h8 * 2 + 0];
          float h2b = c2[mf][nf][h8 * 2 + 1];
          float ga = (h1a / (1.f + __expf(-h1a))) * h2a;
          float gb = (h1b / (1.f + __expf(-h1b))) * h2b;
          size_t o = (size_t)(row0 + rl) * I_DIM + (n0 + wn * 32 + nf * 8 + qp);
          *(__half2*)&g_gated[o] = __floats2half2_rn(ga, gb);
        }
      }
    }
  }
}

// ------------------- GEMM2: out_sorted = gated * W3 -------------------
// BM=128, BN=128, BK=64, 3-stage, warp tile 64x32, interleaved inner loop
__global__ __launch_bounds__(256, 2)
void gemm2_kernel() {
  int tile = blockIdx.y;
  if (tile >= g_ntiles) return;
  extern __shared__ char sm[];
  const int tid = threadIdx.x;
  const int e = g_tile_e[tile];
  const int row0 = g_tile_row[tile];
  const int nrows = g_tile_nrows[tile];
  const int n0 = blockIdx.x * 128;
  const __half* __restrict__ W3 = g_w3h + (size_t)e * I_DIM * D_DIM;

  // A: 1024 chunks (128 rows x 8), 4 per thread
  const __half* ap[4];
  uint32_t ad[4];
#pragma unroll
  for (int q = 0; q < 4; q++) {
    int id = tid + q * 256;
    int r = id >> 3, cc = (id & 7) << 3;
    int srcr = row0 + r; if (srcr >= TRX) srcr = TRX - 1;
    ap[q] = g_gated + (size_t)srcr * I_DIM + cc;
    ad[q] = smem_u32(sm + G2_A) + (r * 72 + cc) * 2;
  }
  // B: 1024 chunks (64 rows x 16), 4 per thread
  const __half* bp[4];
  uint32_t bd[4];
#pragma unroll
  for (int q = 0; q < 4; q++) {
    int id = tid + q * 256;
    int r = id >> 4, cc = (id & 15) << 3;
    bp[q] = W3 + (size_t)r * D_DIM + n0 + cc;
    bd[q] = smem_u32(sm + G2_B) + (r * 136 + cc) * 2;
  }

  float c[4][4][4];
#pragma unroll
  for (int i = 0; i < 4; i++)
#pragma unroll
    for (int j = 0; j < 4; j++)
#pragma unroll
      for (int q = 0; q < 4; q++) c[i][j][q] = 0.f;

  const int lane = tid & 31;
  const int wid = tid >> 5;
  const int wm = wid >> 2;
  const int wn = wid & 3;

  const int NK = I_DIM / BK;  // 48
#pragma unroll
  for (int s = 0; s < STAGES - 1; s++) {
    int k0 = s * BK;
#pragma unroll
    for (int q = 0; q < 4; q++) CP_ASYNC16(ad[q] + s * A_ST, ap[q] + k0);
#pragma unroll
    for (int q = 0; q < 4; q++) CP_ASYNC16(bd[q] + s * B2_ST, bp[q] + (size_t)k0 * D_DIM);
    CP_COMMIT();
  }

#pragma unroll 1
  for (int it = 0; it < NK; it++) {
    const int buf = it % STAGES;
    CP_WAIT(STAGES - 2);
    __syncthreads();
    {
      int pf = it + STAGES - 1;
      if (pf < NK) {
        int sb = pf % STAGES;
        int k0 = pf * BK;
#pragma unroll
        for (int q = 0; q < 4; q++) CP_ASYNC16(ad[q] + sb * A_ST, ap[q] + k0);
#pragma unroll
        for (int q = 0; q < 4; q++) CP_ASYNC16(bd[q] + sb * B2_ST, bp[q] + (size_t)k0 * D_DIM);
      }
      CP_COMMIT();
    }
    const __half* As = (const __half*)(sm + G2_A + buf * A_ST);
    const __half* Bs = (const __half*)(sm + G2_B + buf * B2_ST);

#pragma unroll
    for (int kk = 0; kk < BK; kk += 16) {
      uint32_t a[4][4];
#pragma unroll
      for (int mf = 0; mf < 4; mf++) {
        uint32_t aad = smem_u32(As + (size_t)(wm * 64 + mf * 16 + (lane & 15)) * 72
                                + kk + ((lane >> 4) << 3));
        asm volatile("ldmatrix.sync.aligned.m8n8.x4.shared.b16 {%0,%1,%2,%3}, [%4];"
          : "=r"(a[mf][0]), "=r"(a[mf][1]), "=r"(a[mf][2]), "=r"(a[mf][3]) : "r"(aad));
      }
#pragma unroll
      for (int nf = 0; nf < 4; nf++) {
        uint32_t b[2];
        uint32_t bad = smem_u32(Bs + (size_t)(kk + (lane & 15)) * 136 + wn * 32 + nf * 8);
        asm volatile("ldmatrix.sync.aligned.m8n8.x2.trans.shared.b16 {%0,%1}, [%2];"
          : "=r"(b[0]), "=r"(b[1]) : "r"(bad));
#pragma unroll
        for (int mf = 0; mf < 4; mf++) mma16816(c[mf][nf], a[mf], b);
      }
    }
  }

  const int grp = lane >> 2;
  const int qp  = (lane & 3) << 1;
#pragma unroll
  for (int mf = 0; mf < 4; mf++) {
#pragma unroll
    for (int nf = 0; nf < 4; nf++) {
#pragma unroll
      for (int h8 = 0; h8 < 2; h8++) {
        int rl = wm * 64 + mf * 16 + grp + h8 * 8;
        if (rl < nrows) {
          size_t o = (size_t)(row0 + rl) * D_DIM + (n0 + wn * 32 + nf * 8 + qp);
          float2 v = make_float2(c[mf][nf][h8 * 2 + 0], c[mf][nf][h8 * 2 + 1]);
          *(float2*)&g_outsorted[o] = v;
        }
      }
    }
  }
}

// ------------------- combine + aux -------------------
__global__ void combine_kernel(float* __restrict__ out) {
  int t = blockIdx.x;
  int p0 = g_dest[t * 2 + 0];
  int p1 = g_dest[t * 2 + 1];
  float w0 = g_topk_w[t * 2 + 0];
  float w1 = g_topk_w[t * 2 + 1];
  const float4* s0 = (const float4*)&g_outsorted[(size_t)p0 * D_DIM];
  const float4* s1 = (const float4*)&g_outsorted[(size_t)p1 * D_DIM];
  float4* o = (float4*)(out + (size_t)t * D_DIM);
  int i = threadIdx.x;
  float4 a = s0[i], b = s1[i];
  float4 r;
  r.x = w0 * a.x + w1 * b.x;
  r.y = w0 * a.y + w1 * b.y;
  r.z = w0 * a.z + w1 * b.z;
  r.w = w0 * a.w + w1 * b.w;
  o[i] = r;
}

__global__ void aux_kernel(float* __restrict__ aux) {
  int t = threadIdx.x;
  if (t < E_EXP) aux[t] = (float)g_counts[t] / (float)TRX;
  if (t == 0) {
    float lbl = 0.f;
    for (int e = 0; e < E_EXP; e++) {
      float f = ((float)g_counts[e] / (float)TRX) * ((float)E_EXP / 2.f);
      float pm = g_probs_sum[e] / (float)T_TOK;
      lbl += f * pm;
    }
    aux[E_EXP]     = 0.01f  * lbl;
    aux[E_EXP + 1] = 0.001f * (g_z2_sum / (float)T_TOK);
  }
}

// ------------------------------- launch -------------------------------
extern "C" void kernel_launch(void* const* d_in, const int* in_sizes, int n_in,
                              void* d_out, int out_size) {
  const float* x  = (const float*)d_in[0];
  const float* rw = (const float*)d_in[1];
  const float* w1 = (const float*)d_in[2];
  const float* w2 = (const float*)d_in[3];
  const float* w3 = (const float*)d_in[4];
  float* out = (float*)d_out;

  cudaFuncSetAttribute(gemm1_kernel, cudaFuncAttributeMaxDynamicSharedMemorySize, G1_SMEM);
  cudaFuncSetAttribute(gemm2_kernel, cudaFuncAttributeMaxDynamicSharedMemorySize, G2_SMEM);

  cvt_all_kernel<<<CVT_BLOCKS, 256>>>(w1, w2, w3, x);
  zero_kernel<<<1, 32>>>();
  router_kernel<<<T_TOK / 8, 256>>>(x, rw);
  scan_kernel<<<1, 1>>>();
  scatter_kernel<<<TRX / 256, 256>>>();
  gemm1_kernel<<<dim3(I_DIM / 64, GRID_TILES), 256, G1_SMEM>>>();
  gemm2_kernel<<<dim3(D_DIM / 128, GRID_TILES), 256, G2_SMEM>>>();
  combine_kernel<<<T_TOK, 256>>>(out);
  aux_kernel<<<1, 32>>>(out + (size_t)T_TOK * D_DIM);
}

// round 10
// speedup vs baseline: 1.6136x; 1.0107x over previous
#include <cuda_runtime.h>
#include <cuda_fp16.h>
#include <cstdint>

#define T_TOK 8192
#define D_DIM 1024
#define E_EXP 8
#define I_DIM 3072
#define TRX   16384
#define BM 128
#define BK 64
#define STAGES 3
#define MAXT 144
#define GRID_TILES 136   // max sum ceil(count_e/128)

// ------------------- device scratch (static: no allocation) -------------------
__device__ int    g_topk_idx[TRX];
__device__ float  g_topk_w[TRX];
__device__ int    g_counts[E_EXP];
__device__ int    g_cursor[E_EXP];
__device__ float  g_probs_sum[E_EXP];
__device__ float  g_z2_sum;
__device__ int    g_perm_src[TRX];
__device__ int    g_dest[TRX];
__device__ int    g_tile_e[MAXT];
__device__ int    g_tile_row[MAXT];
__device__ int    g_tile_nrows[MAXT];
__device__ int    g_ntiles;
__device__ __half g_gated[(size_t)TRX * I_DIM];
__device__ float  g_outsorted[(size_t)TRX * D_DIM];
__device__ __half g_w1h[(size_t)E_EXP * D_DIM * I_DIM];
__device__ __half g_w2h[(size_t)E_EXP * D_DIM * I_DIM];
__device__ __half g_w3h[(size_t)E_EXP * I_DIM * D_DIM];
__device__ __half g_xh[(size_t)T_TOK * D_DIM];

__device__ __forceinline__ uint32_t smem_u32(const void* p) {
  return (uint32_t)__cvta_generic_to_shared(p);
}
#define CP_ASYNC16(dst_u32, src_ptr) \
  asm volatile("cp.async.cg.shared.global [%0], [%1], 16;\n" :: "r"(dst_u32), "l"(src_ptr))
#define CP_COMMIT() asm volatile("cp.async.commit_group;\n" ::)
#define CP_WAIT(N)  asm volatile("cp.async.wait_group %0;\n" :: "n"(N))

__device__ __forceinline__ void mma16816(float* c, const uint32_t* a, const uint32_t* b) {
  asm volatile(
    "mma.sync.aligned.m16n8k16.row.col.f32.f16.f16.f32 "
    "{%0,%1,%2,%3}, {%4,%5,%6,%7}, {%8,%9}, {%0,%1,%2,%3};\n"
    : "+f"(c[0]), "+f"(c[1]), "+f"(c[2]), "+f"(c[3])
    : "r"(a[0]), "r"(a[1]), "r"(a[2]), "r"(a[3]), "r"(b[0]), "r"(b[1]));
}
#define LDSM_X4(a, addr) \
  asm volatile("ldmatrix.sync.aligned.m8n8.x4.shared.b16 {%0,%1,%2,%3}, [%4];" \
    : "=r"((a)[0]), "=r"((a)[1]), "=r"((a)[2]), "=r"((a)[3]) : "r"(addr))
#define LDSM_X4T(b, addr) \
  asm volatile("ldmatrix.sync.aligned.m8n8.x4.trans.shared.b16 {%0,%1,%2,%3}, [%4];" \
    : "=r"((b)[0]), "=r"((b)[1]), "=r"((b)[2]), "=r"((b)[3]) : "r"(addr))

// ------------------------------- conversion (merged) -------------------------------
#define WN (E_EXP * D_DIM * I_DIM)
#define XN (T_TOK * D_DIM)
#define WBLK (WN / 2048)
#define XBLK (XN / 2048)
#define CVT_BLOCKS (3 * WBLK + XBLK)

__global__ void cvt_all_kernel(const float* __restrict__ w1, const float* __restrict__ w2,
                               const float* __restrict__ w3, const float* __restrict__ x) {
  int b = blockIdx.x;
  const float* src;
  __half* dst;
  if (b < WBLK)            { src = w1; dst = g_w1h; }
  else if (b < 2 * WBLK)   { src = w2; dst = g_w2h; b -= WBLK; }
  else if (b < 3 * WBLK)   { src = w3; dst = g_w3h; b -= 2 * WBLK; }
  else                     { src = x;  dst = g_xh;  b -= 3 * WBLK; }
  size_t i = ((size_t)b * 256 + threadIdx.x) * 8;
  float4 a = *(const float4*)(src + i);
  float4 c = *(const float4*)(src + i + 4);
  __align__(16) __half2 h[4];
  h[0] = __floats2half2_rn(a.x, a.y);
  h[1] = __floats2half2_rn(a.z, a.w);
  h[2] = __floats2half2_rn(c.x, c.y);
  h[3] = __floats2half2_rn(c.z, c.w);
  *(uint4*)(dst + i) = *(uint4*)h;
}

// ------------------------------- small kernels --------------------------------
__global__ void zero_kernel() {
  int t = threadIdx.x;
  if (t < E_EXP) { g_counts[t] = 0; g_cursor[t] = 0; g_probs_sum[t] = 0.f; }
  if (t == 0) { g_z2_sum = 0.f; g_ntiles = 0; }
}

__global__ void router_kernel(const float* __restrict__ x, const float* __restrict__ rw) {
  int warp = threadIdx.x >> 5;
  int lane = threadIdx.x & 31;
  int token = blockIdx.x * 8 + warp;
  const float* xr = x + (size_t)token * D_DIM;
  float acc[E_EXP];
#pragma unroll
  for (int e = 0; e < E_EXP; e++) acc[e] = 0.f;
  for (int i = lane; i < D_DIM; i += 32) {
    float xv = xr[i];
    const float4* w4 = reinterpret_cast<const float4*>(rw + (size_t)i * E_EXP);
    float4 wa = w4[0], wb = w4[1];
    acc[0] += xv * wa.x; acc[1] += xv * wa.y; acc[2] += xv * wa.z; acc[3] += xv * wa.w;
    acc[4] += xv * wb.x; acc[5] += xv * wb.y; acc[6] += xv * wb.z; acc[7] += xv * wb.w;
  }
#pragma unroll
  for (int e = 0; e < E_EXP; e++) {
#pragma unroll
    for (int o = 16; o > 0; o >>= 1) acc[e] += __shfl_xor_sync(0xffffffffu, acc[e], o);
  }
  if (lane == 0) {
    float m = acc[0];
#pragma unroll
    for (int e = 1; e < E_EXP; e++) m = fmaxf(m, acc[e]);
    float p[E_EXP]; float se = 0.f;
#pragma unroll
    for (int e = 0; e < E_EXP; e++) { p[e] = expf(acc[e] - m); se += p[e]; }
    float inv = 1.f / se;
#pragma unroll
    for (int e = 0; e < E_EXP; e++) p[e] *= inv;
    float z = m + logf(se);
    atomicAdd(&g_z2_sum, z * z);
#pragma unroll
    for (int e = 0; e < E_EXP; e++) atomicAdd(&g_probs_sum[e], p[e]);
    int i0 = 0;
#pragma unroll
    for (int e = 1; e < E_EXP; e++) if (acc[e] > acc[i0]) i0 = e;
    int i1 = (i0 == 0) ? 1 : 0;
#pragma unroll
    for (int e = 0; e < E_EXP; e++) if (e != i0 && acc[e] > acc[i1]) i1 = e;
    float s = p[i0] + p[i1];
    g_topk_idx[token * 2 + 0] = i0;
    g_topk_idx[token * 2 + 1] = i1;
    g_topk_w[token * 2 + 0] = p[i0] / s;
    g_topk_w[token * 2 + 1] = p[i1] / s;
    atomicAdd(&g_counts[i0], 1);
    atomicAdd(&g_counts[i1], 1);
  }
}

__global__ void scan_kernel() {
  if (threadIdx.x == 0) {
    int off = 0, nt = 0;
    for (int e = 0; e < E_EXP; e++) {
      g_cursor[e] = off;
      int c = g_counts[e];
      for (int r = 0; r < c; r += BM) {
        g_tile_e[nt] = e;
        g_tile_row[nt] = off + r;
        g_tile_nrows[nt] = (c - r < BM) ? (c - r) : BM;
        nt++;
      }
      off += c;
    }
    g_ntiles = nt;
  }
}

__global__ void scatter_kernel() {
  int i = blockIdx.x * 256 + threadIdx.x;
  if (i < TRX) {
    int e = g_topk_idx[i];
    int pos = atomicAdd(&g_cursor[e], 1);
    g_perm_src[pos] = i >> 1;
    g_dest[i] = pos;
  }
}

// ------------------- smem layout (BK=64) -------------------
#define A_ST 18432
#define B1_ST 9216
#define G1_A  1024
#define G1_B1 (G1_A + STAGES * A_ST)       // 56320
#define G1_B2 (G1_B1 + STAGES * B1_ST)     // 83968
#define G1_SMEM (G1_B2 + STAGES * B1_ST)   // 111616
#define B2_ST 17408
#define G2_A 0
#define G2_B (STAGES * A_ST)               // 55296
#define G2_SMEM (G2_B + STAGES * B2_ST)    // 107520

// ------------------- GEMM1: gated = silu(Xg*W1) * (Xg*W2) -------------------
// BM=128, BN=64, BK=64, 3-stage, x4.trans B loads, interleaved per-16-col groups
__global__ __launch_bounds__(256, 2)
void gemm1_kernel() {
  int tile = blockIdx.y;
  if (tile >= g_ntiles) return;
  extern __shared__ char sm[];
  const int tid = threadIdx.x;
  const int e = g_tile_e[tile];
  const int row0 = g_tile_row[tile];
  const int nrows = g_tile_nrows[tile];
  const int n0 = blockIdx.x * 64;
  const __half* __restrict__ W1 = g_w1h + (size_t)e * D_DIM * I_DIM;
  const __half* __restrict__ W2 = g_w2h + (size_t)e * D_DIM * I_DIM;

  int* rowtok = (int*)sm;
  if (tid < BM) {
    int r = row0 + tid;
    rowtok[tid] = g_perm_src[r < TRX ? r : TRX - 1];
  }
  __syncthreads();

  const __half* ap[4];
  uint32_t ad[4];
#pragma unroll
  for (int q = 0; q < 4; q++) {
    int id = tid + q * 256;
    int r = id >> 3, cc = (id & 7) << 3;
    ap[q] = g_xh + (size_t)rowtok[r] * D_DIM + cc;
    ad[q] = smem_u32(sm + G1_A) + (r * 72 + cc) * 2;
  }
  const __half* b1p[2]; const __half* b2p[2];
  uint32_t b1d[2], b2d[2];
#pragma unroll
  for (int q = 0; q < 2; q++) {
    int id = tid + q * 256;
    int r = id >> 3, cc = (id & 7) << 3;
    b1p[q] = W1 + (size_t)r * I_DIM + n0 + cc;
    b2p[q] = W2 + (size_t)r * I_DIM + n0 + cc;
    b1d[q] = smem_u32(sm + G1_B1) + (r * 72 + cc) * 2;
    b2d[q] = smem_u32(sm + G1_B2) + (r * 72 + cc) * 2;
  }

  float c1[2][4][4], c2[2][4][4];
#pragma unroll
  for (int i = 0; i < 2; i++)
#pragma unroll
    for (int j = 0; j < 4; j++)
#pragma unroll
      for (int q = 0; q < 4; q++) { c1[i][j][q] = 0.f; c2[i][j][q] = 0.f; }

  const int lane = tid & 31;
  const int wid = tid >> 5;
  const int wm = wid >> 1;
  const int wn = wid & 1;
  // x4.trans lane addressing (validated in R6): row = (lane&7) + ((lane>>3)&1)*8,
  // col offset = ((lane>>4))*8 within the 16-col group
  const int btr = (lane & 7) + ((lane >> 3) & 1) * 8;
  const int btc = wn * 32 + ((lane >> 4) << 3);
  const int atr = wm * 32 + (lane & 15);
  const int atc = (lane >> 4) << 3;

  const int NK = D_DIM / BK;  // 16
#pragma unroll
  for (int s = 0; s < STAGES - 1; s++) {
    int k0 = s * BK;
#pragma unroll
    for (int q = 0; q < 4; q++) CP_ASYNC16(ad[q] + s * A_ST, ap[q] + k0);
#pragma unroll
    for (int q = 0; q < 2; q++) {
      CP_ASYNC16(b1d[q] + s * B1_ST, b1p[q] + (size_t)k0 * I_DIM);
      CP_ASYNC16(b2d[q] + s * B1_ST, b2p[q] + (size_t)k0 * I_DIM);
    }
    CP_COMMIT();
  }

#pragma unroll 1
  for (int it = 0; it < NK; it++) {
    const int buf = it % STAGES;
    CP_WAIT(STAGES - 2);
    __syncthreads();
    {
      int pf = it + STAGES - 1;
      if (pf < NK) {
        int sb = pf % STAGES;
        int k0 = pf * BK;
#pragma unroll
        for (int q = 0; q < 4; q++) CP_ASYNC16(ad[q] + sb * A_ST, ap[q] + k0);
#pragma unroll
        for (int q = 0; q < 2; q++) {
          CP_ASYNC16(b1d[q] + sb * B1_ST, b1p[q] + (size_t)k0 * I_DIM);
          CP_ASYNC16(b2d[q] + sb * B1_ST, b2p[q] + (size_t)k0 * I_DIM);
        }
      }
      CP_COMMIT();
    }
    const __half* As  = (const __half*)(sm + G1_A  + buf * A_ST);
    const __half* B1s = (const __half*)(sm + G1_B1 + buf * B1_ST);
    const __half* B2s = (const __half*)(sm + G1_B2 + buf * B1_ST);

#pragma unroll
    for (int kk = 0; kk < BK; kk += 16) {
      uint32_t a[2][4];
#pragma unroll
      for (int mf = 0; mf < 2; mf++) {
        uint32_t aad = smem_u32(As + (size_t)(atr + mf * 16) * 72 + kk + atc);
        LDSM_X4(a[mf], aad);
      }
#pragma unroll
      for (int nh = 0; nh < 2; nh++) {   // 16-col groups
        uint32_t b[4];
        uint32_t bad1 = smem_u32(B1s + (size_t)(kk + btr) * 72 + btc + nh * 16);
        LDSM_X4T(b, bad1);
        mma16816(c1[0][nh * 2],     a[0], b);
        mma16816(c1[0][nh * 2 + 1], a[0], b + 2);
        mma16816(c1[1][nh * 2],     a[1], b);
        mma16816(c1[1][nh * 2 + 1], a[1], b + 2);
        uint32_t bad2 = smem_u32(B2s + (size_t)(kk + btr) * 72 + btc + nh * 16);
        LDSM_X4T(b, bad2);
        mma16816(c2[0][nh * 2],     a[0], b);
        mma16816(c2[0][nh * 2 + 1], a[0], b + 2);
        mma16816(c2[1][nh * 2],     a[1], b);
        mma16816(c2[1][nh * 2 + 1], a[1], b + 2);
      }
    }
  }

  const int grp = lane >> 2;
  const int qp  = (lane & 3) << 1;
#pragma unroll
  for (int mf = 0; mf < 2; mf++) {
#pragma unroll
    for (int nf = 0; nf < 4; nf++) {
#pragma unroll
      for (int h8 = 0; h8 < 2; h8++) {
        int rl = wm * 32 + mf * 16 + grp + h8 * 8;
        if (rl < nrows) {
          float h1a = c1[mf][nf][h8 * 2 + 0];
          float h1b = c1[mf][nf][h8 * 2 + 1];
          float h2a = c2[mf][nf][h8 * 2 + 0];
          float h2b = c2[mf][nf][h8 * 2 + 1];
          float ga = (h1a / (1.f + __expf(-h1a))) * h2a;
          float gb = (h1b / (1.f + __expf(-h1b))) * h2b;
          size_t o = (size_t)(row0 + rl) * I_DIM + (n0 + wn * 32 + nf * 8 + qp);
          *(__half2*)&g_gated[o] = __floats2half2_rn(ga, gb);
        }
      }
    }
  }
}

// ------------------- GEMM2: out_sorted = gated * W3 -------------------
// BM=128, BN=128, BK=64, 3-stage, warp tile 64x32, x4.trans B loads
__global__ __launch_bounds__(256, 2)
void gemm2_kernel() {
  int tile = blockIdx.y;
  if (tile >= g_ntiles) return;
  extern __shared__ char sm[];
  const int tid = threadIdx.x;
  const int e = g_tile_e[tile];
  const int row0 = g_tile_row[tile];
  const int nrows = g_tile_nrows[tile];
  const int n0 = blockIdx.x * 128;
  const __half* __restrict__ W3 = g_w3h + (size_t)e * I_DIM * D_DIM;

  const __half* ap[4];
  uint32_t ad[4];
#pragma unroll
  for (int q = 0; q < 4; q++) {
    int id = tid + q * 256;
    int r = id >> 3, cc = (id & 7) << 3;
    int srcr = row0 + r; if (srcr >= TRX) srcr = TRX - 1;
    ap[q] = g_gated + (size_t)srcr * I_DIM + cc;
    ad[q] = smem_u32(sm + G2_A) + (r * 72 + cc) * 2;
  }
  const __half* bp[4];
  uint32_t bd[4];
#pragma unroll
  for (int q = 0; q < 4; q++) {
    int id = tid + q * 256;
    int r = id >> 4, cc = (id & 15) << 3;
    bp[q] = W3 + (size_t)r * D_DIM + n0 + cc;
    bd[q] = smem_u32(sm + G2_B) + (r * 136 + cc) * 2;
  }

  float c[4][4][4];
#pragma unroll
  for (int i = 0; i < 4; i++)
#pragma unroll
    for (int j = 0; j < 4; j++)
#pragma unroll
      for (int q = 0; q < 4; q++) c[i][j][q] = 0.f;

  const int lane = tid & 31;
  const int wid = tid >> 5;
  const int wm = wid >> 2;
  const int wn = wid & 3;
  const int btr = (lane & 7) + ((lane >> 3) & 1) * 8;
  const int btc = wn * 32 + ((lane >> 4) << 3);
  const int atr = wm * 64 + (lane & 15);
  const int atc = (lane >> 4) << 3;

  const int NK = I_DIM / BK;  // 48
#pragma unroll
  for (int s = 0; s < STAGES - 1; s++) {
    int k0 = s * BK;
#pragma unroll
    for (int q = 0; q < 4; q++) CP_ASYNC16(ad[q] + s * A_ST, ap[q] + k0);
#pragma unroll
    for (int q = 0; q < 4; q++) CP_ASYNC16(bd[q] + s * B2_ST, bp[q] + (size_t)k0 * D_DIM);
    CP_COMMIT();
  }

#pragma unroll 1
  for (int it = 0; it < NK; it++) {
    const int buf = it % STAGES;
    CP_WAIT(STAGES - 2);
    __syncthreads();
    {
      int pf = it + STAGES - 1;
      if (pf < NK) {
        int sb = pf % STAGES;
        int k0 = pf * BK;
#pragma unroll
        for (int q = 0; q < 4; q++) CP_ASYNC16(ad[q] + sb * A_ST, ap[q] + k0);
#pragma unroll
        for (int q = 0; q < 4; q++) CP_ASYNC16(bd[q] + sb * B2_ST, bp[q] + (size_t)k0 * D_DIM);
      }
      CP_COMMIT();
    }
    const __half* As = (const __half*)(sm + G2_A + buf * A_ST);
    const __half* Bs = (const __half*)(sm + G2_B + buf * B2_ST);

#pragma unroll
    for (int kk = 0; kk < BK; kk += 16) {
      uint32_t a[4][4];
#pragma unroll
      for (int mf = 0; mf < 4; mf++) {
        uint32_t aad = smem_u32(As + (size_t)(atr + mf * 16) * 72 + kk + atc);
        LDSM_X4(a[mf], aad);
      }
#pragma unroll
      for (int nh = 0; nh < 2; nh++) {
        uint32_t b[4];
        uint32_t bad = smem_u32(Bs + (size_t)(kk + btr) * 136 + btc + nh * 16);
        LDSM_X4T(b, bad);
#pragma unroll
        for (int mf = 0; mf < 4; mf++) {
          mma16816(c[mf][nh * 2],     a[mf], b);
          mma16816(c[mf][nh * 2 + 1], a[mf], b + 2);
        }
      }
    }
  }

  const int grp = lane >> 2;
  const int qp  = (lane & 3) << 1;
#pragma unroll
  for (int mf = 0; mf < 4; mf++) {
#pragma unroll
    for (int nf = 0; nf < 4; nf++) {
#pragma unroll
      for (int h8 = 0; h8 < 2; h8++) {
        int rl = wm * 64 + mf * 16 + grp + h8 * 8;
        if (rl < nrows) {
          size_t o = (size_t)(row0 + rl) * D_DIM + (n0 + wn * 32 + nf * 8 + qp);
          float2 v = make_float2(c[mf][nf][h8 * 2 + 0], c[mf][nf][h8 * 2 + 1]);
          *(float2*)&g_outsorted[o] = v;
        }
      }
    }
  }
}

// ------------------- combine + aux -------------------
__global__ void combine_kernel(float* __restrict__ out) {
  int t = blockIdx.x;
  int p0 = g_dest[t * 2 + 0];
  int p1 = g_dest[t * 2 + 1];
  float w0 = g_topk_w[t * 2 + 0];
  float w1 = g_topk_w[t * 2 + 1];
  const float4* s0 = (const float4*)&g_outsorted[(size_t)p0 * D_DIM];
  const float4* s1 = (const float4*)&g_outsorted[(size_t)p1 * D_DIM];
  float4* o = (float4*)(out + (size_t)t * D_DIM);
  int i = threadIdx.x;
  float4 a = s0[i], b = s1[i];
  float4 r;
  r.x = w0 * a.x + w1 * b.x;
  r.y = w0 * a.y + w1 * b.y;
  r.z = w0 * a.z + w1 * b.z;
  r.w = w0 * a.w + w1 * b.w;
  o[i] = r;
}

__global__ void aux_kernel(float* __restrict__ aux) {
  int t = threadIdx.x;
  if (t < E_EXP) aux[t] = (float)g_counts[t] / (float)TRX;
  if (t == 0) {
    float lbl = 0.f;
    for (int e = 0; e < E_EXP; e++) {
      float f = ((float)g_counts[e] / (float)TRX) * ((float)E_EXP / 2.f);
      float pm = g_probs_sum[e] / (float)T_TOK;
      lbl += f * pm;
    }
    aux[E_EXP]     = 0.01f  * lbl;
    aux[E_EXP + 1] = 0.001f * (g_z2_sum / (float)T_TOK);
  }
}

// ------------------------------- launch -------------------------------
extern "C" void kernel_launch(void* const* d_in, const int* in_sizes, int n_in,
                              void* d_out, int out_size) {
  const float* x  = (const float*)d_in[0];
  const float* rw = (const float*)d_in[1];
  const float* w1 = (const float*)d_in[2];
  const float* w2 = (const float*)d_in[3];
  const float* w3 = (const float*)d_in[4];
  float* out = (float*)d_out;

  cudaFuncSetAttribute(gemm1_kernel, cudaFuncAttributeMaxDynamicSharedMemorySize, G1_SMEM);
  cudaFuncSetAttribute(gemm2_kernel, cudaFuncAttributeMaxDynamicSharedMemorySize, G2_SMEM);

  cvt_all_kernel<<<CVT_BLOCKS, 256>>>(w1, w2, w3, x);
  zero_kernel<<<1, 32>>>();
  router_kernel<<<T_TOK / 8, 256>>>(x, rw);
  scan_kernel<<<1, 1>>>();
  scatter_kernel<<<TRX / 256, 256>>>();
  gemm1_kernel<<<dim3(I_DIM / 64, GRID_TILES), 256, G1_SMEM>>>();
  gemm2_kernel<<<dim3(D_DIM / 128, GRID_TILES), 256, G2_SMEM>>>();
  combine_kernel<<<T_TOK, 256>>>(out);
  aux_kernel<<<1, 32>>>(out + (size_t)T_TOK * D_DIM);
}